// round 15
// baseline (speedup 1.0000x reference)
#include <cuda_runtime.h>
#include <cuda_fp16.h>
#include <cstdint>

// Zonotope propagation: D=1024 -> H=4096 -> H=4096 -> O=10
// E2 = W2 @ Baug via single-pass fp16 mma.sync (fp32 acc), rel_err ~6e-6.
// R13: t/v matvecs fused into k3's fp32 A-load path (k3b + side stream gone);
//      k6 merged into k5 via last-block pattern. 4 linear kernels total.

#define DD 1024
#define HH 4096
#define OO 10
#define NE 1024
#define NC3 1027
#define SE3 1056
#define KS3 32
#define NJT 8

#define C_EPS   0.01f
#define C_MEAN  0.1307f
#define C_SIGMA 0.3081f

// ---- device scratch ----
__device__ float g_s1[HH];
__device__ float g_t1[HH];
__device__ float g_v1p[HH];
__device__ float g_d[DD];
__device__ __half g_BTh[(size_t)NE * HH];      // 8.4 MB (BaugT fp16, K-major)
__device__ float g_E2s[(size_t)HH * NE];       // 16.8 MB
__device__ float g_rpart[NJT][HH];
__device__ float g_tcol[HH];
__device__ float g_vcol[HH];
__device__ float g_E3p[KS3 * OO * SE3];
__device__ unsigned int g_cnt5;

// ================= PTX helpers =================
static __device__ __forceinline__ uint32_t smem_u32(const void* p) {
    uint32_t a;
    asm("{ .reg .u64 t; cvta.to.shared.u64 t, %1; cvt.u32.u64 %0, t; }" : "=r"(a) : "l"(p));
    return a;
}
static __device__ __forceinline__ void cp16(uint32_t dst, const void* src) {
    asm volatile("cp.async.cg.shared.global [%0], [%1], 16;" :: "r"(dst), "l"(src));
}
static __device__ __forceinline__ void cp_commit() {
    asm volatile("cp.async.commit_group;" ::: "memory");
}
template <int N> static __device__ __forceinline__ void cp_wait() {
    asm volatile("cp.async.wait_group %0;" :: "n"(N) : "memory");
}
#define LDSM4(r0, r1, r2, r3, addr) \
    asm volatile("ldmatrix.sync.aligned.m8n8.x4.shared.b16 {%0,%1,%2,%3}, [%4];" \
                 : "=r"(r0), "=r"(r1), "=r"(r2), "=r"(r3) : "r"(addr))
#define MMA16816F(c, a, b) \
    asm volatile("mma.sync.aligned.m16n8k16.row.col.f32.f16.f16.f32 " \
                 "{%0,%1,%2,%3}, {%4,%5,%6,%7}, {%8,%9}, {%0,%1,%2,%3};" \
                 : "+f"((c)[0]), "+f"((c)[1]), "+f"((c)[2]), "+f"((c)[3]) \
                 : "r"((a)[0]), "r"((a)[1]), "r"((a)[2]), "r"((a)[3]), \
                   "r"((b)[0]), "r"((b)[1]))
#define STS128(addr, u0, u1, u2, u3) \
    asm volatile("st.shared.v4.b32 [%0], {%1,%2,%3,%4};" \
                 :: "r"(addr), "r"(u0), "r"(u1), "r"(u2), "r"(u3) : "memory")

static __device__ __forceinline__ void relu_params(float v, float r,
                                                   float& s, float& t, float& vn) {
    float u = v + r;
    float l = v - r;
    if (u <= 0.f)       { s = 0.f; t = 0.f; vn = 0.f; }
    else if (l < 0.f)   { float slope = u / (u - l); float term = (1.f - slope) * u * 0.5f;
                          s = slope; t = term; vn = slope * v + term; }
    else                { s = 1.f; t = 0.f; vn = v; }
}
static __device__ __forceinline__ uint32_t h2u(__half2 h) {
    return *reinterpret_cast<uint32_t*>(&h);
}

// ---- K01: fused init + layer-1 ----
__global__ void k01_layer1(const float* __restrict__ in,
                           const float* __restrict__ W1, const float* __restrict__ b1) {
    __shared__ __align__(16) float sv0[DD];
    __shared__ __align__(16) float sd[DD];
    const int tid = threadIdx.x;
    for (int j = tid; j < DD; j += 256) {
        float x  = in[j];
        float up = fminf(x + C_EPS, 1.f);
        float lo = fmaxf(x - C_EPS, 0.f);
        float val = up + lo;
        sv0[j] = (val - C_MEAN) / C_SIGMA;
        sd[j]  = up / C_SIGMA;
    }
    __syncthreads();
    if (blockIdx.x == 0) {
        for (int j = tid; j < DD; j += 256) g_d[j] = sd[j];
    }
    int row  = blockIdx.x * 8 + (tid >> 5);
    int lane = tid & 31;
    const float* w = W1 + (size_t)row * DD;
    float sv = 0.f, sr = 0.f;
    #pragma unroll
    for (int j = lane * 4; j < DD; j += 128) {
        float4 wv = *(const float4*)(w + j);
        float4 v  = *(const float4*)(sv0 + j);
        float4 dd = *(const float4*)(sd + j);
        sv += wv.x * v.x + wv.y * v.y + wv.z * v.z + wv.w * v.w;
        sr += fabsf(wv.x) * dd.x + fabsf(wv.y) * dd.y
            + fabsf(wv.z) * dd.z + fabsf(wv.w) * dd.w;
    }
    #pragma unroll
    for (int o = 16; o; o >>= 1) {
        sv += __shfl_xor_sync(0xffffffffu, sv, o);
        sr += __shfl_xor_sync(0xffffffffu, sr, o);
    }
    if (lane == 0) {
        float v = sv + b1[row];
        float s, t, vn;
        relu_params(v, sr, s, t, vn);
        g_s1[row] = s; g_t1[row] = t; g_v1p[row] = vn;
    }
}

// ---- K2b: BaugT in fp16, 64x64 tiles ----
__global__ void k2b_buildBT(const float* __restrict__ W1) {
    __shared__ float ts[64][65];
    const int k0 = blockIdx.x * 64;
    const int j0 = blockIdx.y * 64;
    const int tid = threadIdx.x;
    {
        const int kr = tid >> 4;
        const int c4 = (tid & 15) * 4;
        #pragma unroll
        for (int r = 0; r < 4; r++) {
            int krow = kr + r * 16;
            float s = g_s1[k0 + krow];
            float4 w = *(const float4*)(W1 + (size_t)(k0 + krow) * DD + j0 + c4);
            ts[krow][c4 + 0] = w.x * s;
            ts[krow][c4 + 1] = w.y * s;
            ts[krow][c4 + 2] = w.z * s;
            ts[krow][c4 + 3] = w.w * s;
        }
    }
    __syncthreads();
    #pragma unroll
    for (int w = 0; w < 2; w++) {
        int idx  = w * 256 + tid;
        int jrow = idx >> 3;
        int seg  = idx & 7;
        float dj = g_d[j0 + jrow];
        __half2 h[4];
        #pragma unroll
        for (int q = 0; q < 4; q++) {
            float a = ts[seg * 8 + q * 2][jrow] * dj;
            float b = ts[seg * 8 + q * 2 + 1][jrow] * dj;
            h[q] = __floats2half2_rn(a, b);
        }
        uint4 out = make_uint4(h2u(h[0]), h2u(h[1]), h2u(h[2]), h2u(h[3]));
        *(uint4*)(&g_BTh[(size_t)(j0 + jrow) * HH + k0 + seg * 8]) = out;
    }
}

// ================== K3: fp16 GEMM + fused t/v matvec (jt==0 CTAs) ============
#define K3_STG 16384
#define K3_SMEM (3 * K3_STG)
#define NKG3 128

__global__ __launch_bounds__(128, 2) void k3_mma(const float* __restrict__ W2) {
    extern __shared__ __align__(1024) unsigned char sm[];
    __shared__ float rs[2][128];
    const int tid  = threadIdx.x;
    const int lane = tid & 31;
    const int wid  = tid >> 5;
    const int warp_m = wid & 1;
    const int warp_n = wid >> 1;
    const int j0 = blockIdx.x * 128;
    const int i0 = blockIdx.y * 128;
    const bool do_tv = (blockIdx.x == 0);
    const uint32_t sbase = smem_u32(sm);

    const int ra = (lane & 7) + (((lane >> 3) & 1) << 3);
    const int ha = lane >> 4;
    const int rb = (lane & 7) + ((lane >> 4) << 3);
    const int hb = (lane >> 3) & 1;
    uint32_t offA[4][2], offB[4][2];
    #pragma unroll
    for (int mf = 0; mf < 4; mf++)
        #pragma unroll
        for (int kk = 0; kk < 2; kk++) {
            int row = warp_m * 64 + mf * 16 + ra;
            int c   = kk * 2 + ha;
            offA[mf][kk] = row * 64 + ((c ^ ((row >> 1) & 3)) << 4);
        }
    #pragma unroll
    for (int nf4 = 0; nf4 < 4; nf4++)
        #pragma unroll
        for (int kk = 0; kk < 2; kk++) {
            int row = warp_n * 64 + nf4 * 16 + rb;
            int c   = kk * 2 + hb;
            offB[nf4][kk] = 8192 + row * 64 + ((c ^ ((row >> 1) & 3)) << 4);
        }

    int crow[4], ccol[4];
    uint32_t csw[4];
    #pragma unroll
    for (int s = 0; s < 4; s++) {
        int q = s * 128 + tid;
        crow[s] = q >> 2; ccol[s] = q & 3;
        csw[s] = crow[s] * 64 + ((ccol[s] ^ ((crow[s] >> 1) & 3)) << 4);
    }

    float4 aA[4][2];
    float tacc[4] = {0.f, 0.f, 0.f, 0.f};
    float vacc[4] = {0.f, 0.f, 0.f, 0.f};

    auto ldgA = [&](int kg) {
        const int kgo = kg * 32;
        #pragma unroll
        for (int s = 0; s < 4; s++) {
            const float* gp = W2 + (size_t)(i0 + crow[s]) * HH + kgo + ccol[s] * 8;
            aA[s][0] = *(const float4*)gp;
            aA[s][1] = *(const float4*)(gp + 4);
        }
        if (do_tv) {
            #pragma unroll
            for (int s = 0; s < 4; s++) {
                const int ko = kgo + ccol[s] * 8;
                float4 t0 = *(const float4*)(g_t1 + ko);
                float4 t1 = *(const float4*)(g_t1 + ko + 4);
                float4 p0 = *(const float4*)(g_v1p + ko);
                float4 p1 = *(const float4*)(g_v1p + ko + 4);
                tacc[s] += aA[s][0].x * t0.x + aA[s][0].y * t0.y
                         + aA[s][0].z * t0.z + aA[s][0].w * t0.w
                         + aA[s][1].x * t1.x + aA[s][1].y * t1.y
                         + aA[s][1].z * t1.z + aA[s][1].w * t1.w;
                vacc[s] += aA[s][0].x * p0.x + aA[s][0].y * p0.y
                         + aA[s][0].z * p0.z + aA[s][0].w * p0.w
                         + aA[s][1].x * p1.x + aA[s][1].y * p1.y
                         + aA[s][1].z * p1.z + aA[s][1].w * p1.w;
            }
        }
    };
    auto stsA = [&](int stage) {
        const uint32_t base = sbase + stage * K3_STG;
        #pragma unroll
        for (int s = 0; s < 4; s++) {
            __half2 h0 = __floats2half2_rn(aA[s][0].x, aA[s][0].y);
            __half2 h1 = __floats2half2_rn(aA[s][0].z, aA[s][0].w);
            __half2 h2 = __floats2half2_rn(aA[s][1].x, aA[s][1].y);
            __half2 h3 = __floats2half2_rn(aA[s][1].z, aA[s][1].w);
            STS128(base + csw[s], h2u(h0), h2u(h1), h2u(h2), h2u(h3));
        }
    };
    auto cpB = [&](int stage, int kg) {
        const uint32_t base = sbase + stage * K3_STG + 8192;
        const int kgo = kg * 32;
        #pragma unroll
        for (int s = 0; s < 4; s++)
            cp16(base + csw[s], g_BTh + (size_t)(j0 + crow[s]) * HH + kgo + ccol[s] * 8);
        cp_commit();
    };

    float acc[4][8][4];
    #pragma unroll
    for (int mf = 0; mf < 4; mf++)
        #pragma unroll
        for (int nf = 0; nf < 8; nf++)
            #pragma unroll
            for (int q = 0; q < 4; q++) acc[mf][nf][q] = 0.f;

    ldgA(0); stsA(0); cpB(0, 0);
    ldgA(1); stsA(1); cpB(1, 1);
    ldgA(2);

    for (int kg = 0; kg < NKG3; ++kg) {
        if (kg + 1 == NKG3) cp_wait<0>();
        else                cp_wait<1>();
        __syncthreads();
        if (kg + 2 < NKG3) {
            const int ps = (kg + 2) % 3;
            stsA(ps);
            if (kg + 3 < NKG3) ldgA(kg + 3);
            cpB(ps, kg + 2);
        }
        const uint32_t base = sbase + (kg % 3) * K3_STG;
        #pragma unroll
        for (int kk = 0; kk < 2; kk++) {
            uint32_t a[4][4], bh[8][2];
            #pragma unroll
            for (int mf = 0; mf < 4; mf++)
                LDSM4(a[mf][0], a[mf][1], a[mf][2], a[mf][3], base + offA[mf][kk]);
            #pragma unroll
            for (int nf4 = 0; nf4 < 4; nf4++) {
                uint32_t r0, r1, r2, r3;
                LDSM4(r0, r1, r2, r3, base + offB[nf4][kk]);
                bh[nf4 * 2][0] = r0;     bh[nf4 * 2][1] = r1;
                bh[nf4 * 2 + 1][0] = r2; bh[nf4 * 2 + 1][1] = r3;
            }
            #pragma unroll
            for (int mf = 0; mf < 4; mf++)
                #pragma unroll
                for (int nf = 0; nf < 8; nf++)
                    MMA16816F(acc[mf][nf], a[mf], bh[nf]);
        }
    }

    // fused t/v writeback (jt==0 CTAs): reduce across the 4 lanes per row
    if (do_tv) {
        #pragma unroll
        for (int s = 0; s < 4; s++) {
            float t = tacc[s], v = vacc[s];
            t += __shfl_xor_sync(0xffffffffu, t, 1);
            t += __shfl_xor_sync(0xffffffffu, t, 2);
            v += __shfl_xor_sync(0xffffffffu, v, 1);
            v += __shfl_xor_sync(0xffffffffu, v, 2);
            if ((lane & 3) == 0) {
                g_tcol[i0 + crow[s]] = t;
                g_vcol[i0 + crow[s]] = v;
            }
        }
    }

    // epilogue: store E2 tile + fused per-row |.| partial sums
    const int er = lane >> 2;
    const int ec = (lane & 3) * 2;
    #pragma unroll
    for (int mf = 0; mf < 4; mf++) {
        float sa = 0.f, sb = 0.f;
        #pragma unroll
        for (int nf = 0; nf < 8; nf++) {
            int row = i0 + warp_m * 64 + mf * 16 + er;
            int col = j0 + warp_n * 64 + nf * 8 + ec;
            *(float2*)(g_E2s + (size_t)row * NE + col)       = make_float2(acc[mf][nf][0], acc[mf][nf][1]);
            *(float2*)(g_E2s + (size_t)(row + 8) * NE + col) = make_float2(acc[mf][nf][2], acc[mf][nf][3]);
            sa += fabsf(acc[mf][nf][0]) + fabsf(acc[mf][nf][1]);
            sb += fabsf(acc[mf][nf][2]) + fabsf(acc[mf][nf][3]);
        }
        sa += __shfl_xor_sync(0xffffffffu, sa, 1);
        sa += __shfl_xor_sync(0xffffffffu, sa, 2);
        sb += __shfl_xor_sync(0xffffffffu, sb, 1);
        sb += __shfl_xor_sync(0xffffffffu, sb, 2);
        if ((lane & 3) == 0) {
            rs[warp_n][warp_m * 64 + mf * 16 + er]     = sa;
            rs[warp_n][warp_m * 64 + mf * 16 + 8 + er] = sb;
        }
    }
    __syncthreads();
    {
        int row = tid;
        float v = rs[0][row] + rs[1][row];
        g_rpart[blockIdx.x][i0 + row] = v;
    }
}

// ---- K56: layer-3 partial GEMM + inline ReLU params + last-block finalize ----
__global__ void k56_e3(const float* __restrict__ W3, const float* __restrict__ b2,
                       const float* __restrict__ b3, float* __restrict__ out) {
    __shared__ float w3s[OO][128];
    __shared__ float s2s[128];
    __shared__ float t2s[128];
    __shared__ float v2s[128];
    __shared__ bool last;
    const int jt = blockIdx.x, ks = blockIdx.y;
    const int k0 = ks * 128;
    const int tid = threadIdx.x;

    // inline relu params for this k-chunk
    {
        int row = k0 + tid;
        float sr = 0.f;
        #pragma unroll
        for (int p = 0; p < NJT; p++) sr += g_rpart[p][row];
        sr += fabsf(g_tcol[row]);
        float v = g_vcol[row] + b2[row];
        float s, t, vn;
        relu_params(v, sr, s, t, vn);
        s2s[tid] = s; t2s[tid] = t; v2s[tid] = vn;
    }
    for (int idx = tid; idx < OO * 128; idx += 128) {
        int i = idx >> 7, kk = idx & 127;
        w3s[i][kk] = W3[(size_t)i * HH + k0 + kk];
    }
    __syncthreads();

    const int j = jt * 128 + tid;
    float acc[OO];
    #pragma unroll
    for (int i = 0; i < OO; i++) acc[i] = 0.f;

    if (j < 1024) {
        const float* e = g_E2s + (size_t)k0 * NE + j;
        for (int kk = 0; kk < 128; ++kk) {
            float bval = s2s[kk] * e[(size_t)kk * NE];
            #pragma unroll
            for (int i = 0; i < OO; i++) acc[i] += w3s[i][kk] * bval;
        }
    } else if (j == 1024) {
        for (int kk = 0; kk < 128; ++kk) {
            float bval = s2s[kk] * g_tcol[k0 + kk];
            #pragma unroll
            for (int i = 0; i < OO; i++) acc[i] += w3s[i][kk] * bval;
        }
    } else if (j == 1025) {
        for (int kk = 0; kk < 128; ++kk) {
            float bval = t2s[kk];
            #pragma unroll
            for (int i = 0; i < OO; i++) acc[i] += w3s[i][kk] * bval;
        }
    } else if (j == 1026) {
        for (int kk = 0; kk < 128; ++kk) {
            float bval = v2s[kk];
            #pragma unroll
            for (int i = 0; i < OO; i++) acc[i] += w3s[i][kk] * bval;
        }
    }
    if (j < NC3) {
        #pragma unroll
        for (int i = 0; i < OO; i++)
            g_E3p[((size_t)ks * OO + i) * SE3 + j] = acc[i];
    }

    // last-block finalize (deterministic: fixed reduction order)
    __threadfence();
    __syncthreads();
    if (tid == 0) {
        unsigned int ticket = atomicAdd(&g_cnt5, 1u);
        last = (ticket == 9u * KS3 - 1u);
    }
    __syncthreads();
    if (!last) return;

    __shared__ float red[128];
    for (int i = 0; i < OO; i++) {
        float racc = 0.f;
        float vterm = 0.f;
        for (int jj = tid; jj < NC3; jj += 128) {
            float s = 0.f;
            #pragma unroll
            for (int kss = 0; kss < KS3; kss++)
                s += g_E3p[((size_t)kss * OO + i) * SE3 + jj];
            if (jj < 1026) racc += fabsf(s);
            else           vterm = s + b3[i];
        }
        red[tid] = racc;
        __syncthreads();
        for (int o = 64; o; o >>= 1) {
            if (tid < o) red[tid] += red[tid + o];
            __syncthreads();
        }
        if (tid == 0) {
            // vterm lives in the thread that handled jj==1026 (tid 2); fetch via smem
        }
        __shared__ float vsh;
        if ((1026 % 128) == tid) vsh = vterm;
        __syncthreads();
        if (tid == 0) {
            float v = vsh, r = red[0];
            out[i]      = v + r;
            out[10 + i] = v - r;
        }
        __syncthreads();
    }
    if (tid == 0) g_cnt5 = 0;   // reset for next graph replay
}

extern "C" void kernel_launch(void* const* d_in, const int* in_sizes, int n_in,
                              void* d_out, int out_size) {
    const float* inputs = (const float*)d_in[0];
    const float* W1     = (const float*)d_in[1];
    const float* b1     = (const float*)d_in[2];
    const float* W2     = (const float*)d_in[3];
    const float* b2     = (const float*)d_in[4];
    const float* W3     = (const float*)d_in[5];
    const float* b3     = (const float*)d_in[6];
    float* out = (float*)d_out;

    static bool init_done = false;
    if (!init_done) {
        cudaFuncSetAttribute(k3_mma, cudaFuncAttributeMaxDynamicSharedMemorySize, K3_SMEM);
        unsigned int zero = 0;
        cudaMemcpyToSymbolAsync(g_cnt5, &zero, sizeof(zero), 0, cudaMemcpyHostToDevice, 0);
        init_done = true;
    }

    k01_layer1<<<HH / 8, 256>>>(inputs, W1, b1);
    dim3 g2b(HH / 64, DD / 64);
    k2b_buildBT<<<g2b, 256>>>(W1);
    dim3 g3(NE / 128, HH / 128);
    k3_mma<<<g3, 128, K3_SMEM>>>(W2);
    dim3 g5(9, KS3);
    k56_e3<<<g5, 128>>>(W3, b2, b3, out);
}

// round 16
// speedup vs baseline: 1.3936x; 1.3936x over previous
#include <cuda_runtime.h>
#include <cuda_fp16.h>
#include <cstdint>

// Zonotope propagation: D=1024 -> H=4096 -> H=4096 -> O=10
// E2 = W2 @ Baug via single-pass fp16 mma.sync (fp32 acc), rel_err ~6e-6.
// R15: keep R13's t/v-fusion into k3 (no k3b, no side stream) + inline ReLU
//      params in k5; REVERT finalize to separate 10-block k6 (the single-
//      block last-CTA reduction was a 130us serial tail -- R13's regression).

#define DD 1024
#define HH 4096
#define OO 10
#define NE 1024
#define NC3 1027
#define SE3 1056
#define KS3 32
#define NJT 8

#define C_EPS   0.01f
#define C_MEAN  0.1307f
#define C_SIGMA 0.3081f

// ---- device scratch ----
__device__ float g_s1[HH];
__device__ float g_t1[HH];
__device__ float g_v1p[HH];
__device__ float g_d[DD];
__device__ __half g_BTh[(size_t)NE * HH];      // 8.4 MB (BaugT fp16, K-major)
__device__ float g_E2s[(size_t)HH * NE];       // 16.8 MB
__device__ float g_rpart[NJT][HH];
__device__ float g_tcol[HH];
__device__ float g_vcol[HH];
__device__ float g_E3p[KS3 * OO * SE3];

// ================= PTX helpers =================
static __device__ __forceinline__ uint32_t smem_u32(const void* p) {
    uint32_t a;
    asm("{ .reg .u64 t; cvta.to.shared.u64 t, %1; cvt.u32.u64 %0, t; }" : "=r"(a) : "l"(p));
    return a;
}
static __device__ __forceinline__ void cp16(uint32_t dst, const void* src) {
    asm volatile("cp.async.cg.shared.global [%0], [%1], 16;" :: "r"(dst), "l"(src));
}
static __device__ __forceinline__ void cp_commit() {
    asm volatile("cp.async.commit_group;" ::: "memory");
}
template <int N> static __device__ __forceinline__ void cp_wait() {
    asm volatile("cp.async.wait_group %0;" :: "n"(N) : "memory");
}
#define LDSM4(r0, r1, r2, r3, addr) \
    asm volatile("ldmatrix.sync.aligned.m8n8.x4.shared.b16 {%0,%1,%2,%3}, [%4];" \
                 : "=r"(r0), "=r"(r1), "=r"(r2), "=r"(r3) : "r"(addr))
#define MMA16816F(c, a, b) \
    asm volatile("mma.sync.aligned.m16n8k16.row.col.f32.f16.f16.f32 " \
                 "{%0,%1,%2,%3}, {%4,%5,%6,%7}, {%8,%9}, {%0,%1,%2,%3};" \
                 : "+f"((c)[0]), "+f"((c)[1]), "+f"((c)[2]), "+f"((c)[3]) \
                 : "r"((a)[0]), "r"((a)[1]), "r"((a)[2]), "r"((a)[3]), \
                   "r"((b)[0]), "r"((b)[1]))
#define STS128(addr, u0, u1, u2, u3) \
    asm volatile("st.shared.v4.b32 [%0], {%1,%2,%3,%4};" \
                 :: "r"(addr), "r"(u0), "r"(u1), "r"(u2), "r"(u3) : "memory")

static __device__ __forceinline__ void relu_params(float v, float r,
                                                   float& s, float& t, float& vn) {
    float u = v + r;
    float l = v - r;
    if (u <= 0.f)       { s = 0.f; t = 0.f; vn = 0.f; }
    else if (l < 0.f)   { float slope = u / (u - l); float term = (1.f - slope) * u * 0.5f;
                          s = slope; t = term; vn = slope * v + term; }
    else                { s = 1.f; t = 0.f; vn = v; }
}
static __device__ __forceinline__ uint32_t h2u(__half2 h) {
    return *reinterpret_cast<uint32_t*>(&h);
}

// ---- K01: fused init + layer-1 ----
__global__ void k01_layer1(const float* __restrict__ in,
                           const float* __restrict__ W1, const float* __restrict__ b1) {
    __shared__ __align__(16) float sv0[DD];
    __shared__ __align__(16) float sd[DD];
    const int tid = threadIdx.x;
    for (int j = tid; j < DD; j += 256) {
        float x  = in[j];
        float up = fminf(x + C_EPS, 1.f);
        float lo = fmaxf(x - C_EPS, 0.f);
        float val = up + lo;
        sv0[j] = (val - C_MEAN) / C_SIGMA;
        sd[j]  = up / C_SIGMA;
    }
    __syncthreads();
    if (blockIdx.x == 0) {
        for (int j = tid; j < DD; j += 256) g_d[j] = sd[j];
    }
    int row  = blockIdx.x * 8 + (tid >> 5);
    int lane = tid & 31;
    const float* w = W1 + (size_t)row * DD;
    float sv = 0.f, sr = 0.f;
    #pragma unroll
    for (int j = lane * 4; j < DD; j += 128) {
        float4 wv = *(const float4*)(w + j);
        float4 v  = *(const float4*)(sv0 + j);
        float4 dd = *(const float4*)(sd + j);
        sv += wv.x * v.x + wv.y * v.y + wv.z * v.z + wv.w * v.w;
        sr += fabsf(wv.x) * dd.x + fabsf(wv.y) * dd.y
            + fabsf(wv.z) * dd.z + fabsf(wv.w) * dd.w;
    }
    #pragma unroll
    for (int o = 16; o; o >>= 1) {
        sv += __shfl_xor_sync(0xffffffffu, sv, o);
        sr += __shfl_xor_sync(0xffffffffu, sr, o);
    }
    if (lane == 0) {
        float v = sv + b1[row];
        float s, t, vn;
        relu_params(v, sr, s, t, vn);
        g_s1[row] = s; g_t1[row] = t; g_v1p[row] = vn;
    }
}

// ---- K2b: BaugT in fp16, 64x64 tiles ----
__global__ void k2b_buildBT(const float* __restrict__ W1) {
    __shared__ float ts[64][65];
    const int k0 = blockIdx.x * 64;
    const int j0 = blockIdx.y * 64;
    const int tid = threadIdx.x;
    {
        const int kr = tid >> 4;
        const int c4 = (tid & 15) * 4;
        #pragma unroll
        for (int r = 0; r < 4; r++) {
            int krow = kr + r * 16;
            float s = g_s1[k0 + krow];
            float4 w = *(const float4*)(W1 + (size_t)(k0 + krow) * DD + j0 + c4);
            ts[krow][c4 + 0] = w.x * s;
            ts[krow][c4 + 1] = w.y * s;
            ts[krow][c4 + 2] = w.z * s;
            ts[krow][c4 + 3] = w.w * s;
        }
    }
    __syncthreads();
    #pragma unroll
    for (int w = 0; w < 2; w++) {
        int idx  = w * 256 + tid;
        int jrow = idx >> 3;
        int seg  = idx & 7;
        float dj = g_d[j0 + jrow];
        __half2 h[4];
        #pragma unroll
        for (int q = 0; q < 4; q++) {
            float a = ts[seg * 8 + q * 2][jrow] * dj;
            float b = ts[seg * 8 + q * 2 + 1][jrow] * dj;
            h[q] = __floats2half2_rn(a, b);
        }
        uint4 out = make_uint4(h2u(h[0]), h2u(h[1]), h2u(h[2]), h2u(h[3]));
        *(uint4*)(&g_BTh[(size_t)(j0 + jrow) * HH + k0 + seg * 8]) = out;
    }
}

// ================== K3: fp16 GEMM + fused t/v matvec (jt==0 CTAs) ============
#define K3_STG 16384
#define K3_SMEM (3 * K3_STG)
#define NKG3 128

__global__ __launch_bounds__(128, 2) void k3_mma(const float* __restrict__ W2) {
    extern __shared__ __align__(1024) unsigned char sm[];
    __shared__ float rs[2][128];
    const int tid  = threadIdx.x;
    const int lane = tid & 31;
    const int wid  = tid >> 5;
    const int warp_m = wid & 1;
    const int warp_n = wid >> 1;
    const int j0 = blockIdx.x * 128;
    const int i0 = blockIdx.y * 128;
    const bool do_tv = (blockIdx.x == 0);
    const uint32_t sbase = smem_u32(sm);

    const int ra = (lane & 7) + (((lane >> 3) & 1) << 3);
    const int ha = lane >> 4;
    const int rb = (lane & 7) + ((lane >> 4) << 3);
    const int hb = (lane >> 3) & 1;
    uint32_t offA[4][2], offB[4][2];
    #pragma unroll
    for (int mf = 0; mf < 4; mf++)
        #pragma unroll
        for (int kk = 0; kk < 2; kk++) {
            int row = warp_m * 64 + mf * 16 + ra;
            int c   = kk * 2 + ha;
            offA[mf][kk] = row * 64 + ((c ^ ((row >> 1) & 3)) << 4);
        }
    #pragma unroll
    for (int nf4 = 0; nf4 < 4; nf4++)
        #pragma unroll
        for (int kk = 0; kk < 2; kk++) {
            int row = warp_n * 64 + nf4 * 16 + rb;
            int c   = kk * 2 + hb;
            offB[nf4][kk] = 8192 + row * 64 + ((c ^ ((row >> 1) & 3)) << 4);
        }

    int crow[4], ccol[4];
    uint32_t csw[4];
    #pragma unroll
    for (int s = 0; s < 4; s++) {
        int q = s * 128 + tid;
        crow[s] = q >> 2; ccol[s] = q & 3;
        csw[s] = crow[s] * 64 + ((ccol[s] ^ ((crow[s] >> 1) & 3)) << 4);
    }

    float4 aA[4][2];
    float tacc[4] = {0.f, 0.f, 0.f, 0.f};
    float vacc[4] = {0.f, 0.f, 0.f, 0.f};

    auto ldgA = [&](int kg) {
        const int kgo = kg * 32;
        #pragma unroll
        for (int s = 0; s < 4; s++) {
            const float* gp = W2 + (size_t)(i0 + crow[s]) * HH + kgo + ccol[s] * 8;
            aA[s][0] = *(const float4*)gp;
            aA[s][1] = *(const float4*)(gp + 4);
        }
        if (do_tv) {
            #pragma unroll
            for (int s = 0; s < 4; s++) {
                const int ko = kgo + ccol[s] * 8;
                float4 t0 = *(const float4*)(g_t1 + ko);
                float4 t1 = *(const float4*)(g_t1 + ko + 4);
                float4 p0 = *(const float4*)(g_v1p + ko);
                float4 p1 = *(const float4*)(g_v1p + ko + 4);
                tacc[s] += aA[s][0].x * t0.x + aA[s][0].y * t0.y
                         + aA[s][0].z * t0.z + aA[s][0].w * t0.w
                         + aA[s][1].x * t1.x + aA[s][1].y * t1.y
                         + aA[s][1].z * t1.z + aA[s][1].w * t1.w;
                vacc[s] += aA[s][0].x * p0.x + aA[s][0].y * p0.y
                         + aA[s][0].z * p0.z + aA[s][0].w * p0.w
                         + aA[s][1].x * p1.x + aA[s][1].y * p1.y
                         + aA[s][1].z * p1.z + aA[s][1].w * p1.w;
            }
        }
    };
    auto stsA = [&](int stage) {
        const uint32_t base = sbase + stage * K3_STG;
        #pragma unroll
        for (int s = 0; s < 4; s++) {
            __half2 h0 = __floats2half2_rn(aA[s][0].x, aA[s][0].y);
            __half2 h1 = __floats2half2_rn(aA[s][0].z, aA[s][0].w);
            __half2 h2 = __floats2half2_rn(aA[s][1].x, aA[s][1].y);
            __half2 h3 = __floats2half2_rn(aA[s][1].z, aA[s][1].w);
            STS128(base + csw[s], h2u(h0), h2u(h1), h2u(h2), h2u(h3));
        }
    };
    auto cpB = [&](int stage, int kg) {
        const uint32_t base = sbase + stage * K3_STG + 8192;
        const int kgo = kg * 32;
        #pragma unroll
        for (int s = 0; s < 4; s++)
            cp16(base + csw[s], g_BTh + (size_t)(j0 + crow[s]) * HH + kgo + ccol[s] * 8);
        cp_commit();
    };

    float acc[4][8][4];
    #pragma unroll
    for (int mf = 0; mf < 4; mf++)
        #pragma unroll
        for (int nf = 0; nf < 8; nf++)
            #pragma unroll
            for (int q = 0; q < 4; q++) acc[mf][nf][q] = 0.f;

    ldgA(0); stsA(0); cpB(0, 0);
    ldgA(1); stsA(1); cpB(1, 1);
    ldgA(2);

    for (int kg = 0; kg < NKG3; ++kg) {
        if (kg + 1 == NKG3) cp_wait<0>();
        else                cp_wait<1>();
        __syncthreads();
        if (kg + 2 < NKG3) {
            const int ps = (kg + 2) % 3;
            stsA(ps);
            if (kg + 3 < NKG3) ldgA(kg + 3);
            cpB(ps, kg + 2);
        }
        const uint32_t base = sbase + (kg % 3) * K3_STG;
        #pragma unroll
        for (int kk = 0; kk < 2; kk++) {
            uint32_t a[4][4], bh[8][2];
            #pragma unroll
            for (int mf = 0; mf < 4; mf++)
                LDSM4(a[mf][0], a[mf][1], a[mf][2], a[mf][3], base + offA[mf][kk]);
            #pragma unroll
            for (int nf4 = 0; nf4 < 4; nf4++) {
                uint32_t r0, r1, r2, r3;
                LDSM4(r0, r1, r2, r3, base + offB[nf4][kk]);
                bh[nf4 * 2][0] = r0;     bh[nf4 * 2][1] = r1;
                bh[nf4 * 2 + 1][0] = r2; bh[nf4 * 2 + 1][1] = r3;
            }
            #pragma unroll
            for (int mf = 0; mf < 4; mf++)
                #pragma unroll
                for (int nf = 0; nf < 8; nf++)
                    MMA16816F(acc[mf][nf], a[mf], bh[nf]);
        }
    }

    // fused t/v writeback (jt==0 CTAs)
    if (do_tv) {
        #pragma unroll
        for (int s = 0; s < 4; s++) {
            float t = tacc[s], v = vacc[s];
            t += __shfl_xor_sync(0xffffffffu, t, 1);
            t += __shfl_xor_sync(0xffffffffu, t, 2);
            v += __shfl_xor_sync(0xffffffffu, v, 1);
            v += __shfl_xor_sync(0xffffffffu, v, 2);
            if ((lane & 3) == 0) {
                g_tcol[i0 + crow[s]] = t;
                g_vcol[i0 + crow[s]] = v;
            }
        }
    }

    // epilogue: store E2 tile + fused per-row |.| partial sums
    const int er = lane >> 2;
    const int ec = (lane & 3) * 2;
    #pragma unroll
    for (int mf = 0; mf < 4; mf++) {
        float sa = 0.f, sb = 0.f;
        #pragma unroll
        for (int nf = 0; nf < 8; nf++) {
            int row = i0 + warp_m * 64 + mf * 16 + er;
            int col = j0 + warp_n * 64 + nf * 8 + ec;
            *(float2*)(g_E2s + (size_t)row * NE + col)       = make_float2(acc[mf][nf][0], acc[mf][nf][1]);
            *(float2*)(g_E2s + (size_t)(row + 8) * NE + col) = make_float2(acc[mf][nf][2], acc[mf][nf][3]);
            sa += fabsf(acc[mf][nf][0]) + fabsf(acc[mf][nf][1]);
            sb += fabsf(acc[mf][nf][2]) + fabsf(acc[mf][nf][3]);
        }
        sa += __shfl_xor_sync(0xffffffffu, sa, 1);
        sa += __shfl_xor_sync(0xffffffffu, sa, 2);
        sb += __shfl_xor_sync(0xffffffffu, sb, 1);
        sb += __shfl_xor_sync(0xffffffffu, sb, 2);
        if ((lane & 3) == 0) {
            rs[warp_n][warp_m * 64 + mf * 16 + er]     = sa;
            rs[warp_n][warp_m * 64 + mf * 16 + 8 + er] = sb;
        }
    }
    __syncthreads();
    {
        int row = tid;
        float v = rs[0][row] + rs[1][row];
        g_rpart[blockIdx.x][i0 + row] = v;
    }
}

// ---- K5: layer-3 partial GEMM + inline ReLU params ----
__global__ void k5_e3(const float* __restrict__ W3, const float* __restrict__ b2) {
    __shared__ float w3s[OO][128];
    __shared__ float s2s[128];
    __shared__ float t2s[128];
    __shared__ float v2s[128];
    const int jt = blockIdx.x, ks = blockIdx.y;
    const int k0 = ks * 128;
    const int tid = threadIdx.x;

    {
        int row = k0 + tid;
        float sr = 0.f;
        #pragma unroll
        for (int p = 0; p < NJT; p++) sr += g_rpart[p][row];
        sr += fabsf(g_tcol[row]);
        float v = g_vcol[row] + b2[row];
        float s, t, vn;
        relu_params(v, sr, s, t, vn);
        s2s[tid] = s; t2s[tid] = t; v2s[tid] = vn;
    }
    for (int idx = tid; idx < OO * 128; idx += 128) {
        int i = idx >> 7, kk = idx & 127;
        w3s[i][kk] = W3[(size_t)i * HH + k0 + kk];
    }
    __syncthreads();

    const int j = jt * 128 + tid;
    float acc[OO];
    #pragma unroll
    for (int i = 0; i < OO; i++) acc[i] = 0.f;

    if (j < 1024) {
        const float* e = g_E2s + (size_t)k0 * NE + j;
        for (int kk = 0; kk < 128; ++kk) {
            float bval = s2s[kk] * e[(size_t)kk * NE];
            #pragma unroll
            for (int i = 0; i < OO; i++) acc[i] += w3s[i][kk] * bval;
        }
    } else if (j == 1024) {
        for (int kk = 0; kk < 128; ++kk) {
            float bval = s2s[kk] * g_tcol[k0 + kk];
            #pragma unroll
            for (int i = 0; i < OO; i++) acc[i] += w3s[i][kk] * bval;
        }
    } else if (j == 1025) {
        for (int kk = 0; kk < 128; ++kk) {
            float bval = t2s[kk];
            #pragma unroll
            for (int i = 0; i < OO; i++) acc[i] += w3s[i][kk] * bval;
        }
    } else if (j == 1026) {
        for (int kk = 0; kk < 128; ++kk) {
            float bval = v2s[kk];
            #pragma unroll
            for (int i = 0; i < OO; i++) acc[i] += w3s[i][kk] * bval;
        }
    }
    if (j < NC3) {
        #pragma unroll
        for (int i = 0; i < OO; i++)
            g_E3p[((size_t)ks * OO + i) * SE3 + j] = acc[i];
    }
}

// ---- K6: final bounds (10 parallel blocks) ----
__global__ void k6_final(const float* __restrict__ b3, float* __restrict__ out) {
    const int i = blockIdx.x;
    const int tid = threadIdx.x;
    __shared__ float red[256];
    __shared__ float vsh;
    float racc = 0.f;
    for (int j = tid; j < NC3; j += 256) {
        float s = 0.f;
        #pragma unroll
        for (int ks = 0; ks < KS3; ks++) s += g_E3p[((size_t)ks * OO + i) * SE3 + j];
        if (j < 1026) racc += fabsf(s);
        else          vsh = s + b3[i];
    }
    red[tid] = racc;
    __syncthreads();
    for (int o = 128; o; o >>= 1) {
        if (tid < o) red[tid] += red[tid + o];
        __syncthreads();
    }
    if (tid == 0) {
        float v = vsh, r = red[0];
        out[i]      = v + r;
        out[10 + i] = v - r;
    }
}

extern "C" void kernel_launch(void* const* d_in, const int* in_sizes, int n_in,
                              void* d_out, int out_size) {
    const float* inputs = (const float*)d_in[0];
    const float* W1     = (const float*)d_in[1];
    const float* b1     = (const float*)d_in[2];
    const float* W2     = (const float*)d_in[3];
    const float* b2     = (const float*)d_in[4];
    const float* W3     = (const float*)d_in[5];
    const float* b3     = (const float*)d_in[6];
    float* out = (float*)d_out;

    static bool init_done = false;
    if (!init_done) {
        cudaFuncSetAttribute(k3_mma, cudaFuncAttributeMaxDynamicSharedMemorySize, K3_SMEM);
        init_done = true;
    }

    k01_layer1<<<HH / 8, 256>>>(inputs, W1, b1);
    dim3 g2b(HH / 64, DD / 64);
    k2b_buildBT<<<g2b, 256>>>(W1);
    dim3 g3(NE / 128, HH / 128);
    k3_mma<<<g3, 128, K3_SMEM>>>(W2);
    dim3 g5(9, KS3);
    k5_e3<<<g5, 128>>>(W3, b2);
    k6_final<<<OO, 256>>>(b3, out);
}

// round 17
// speedup vs baseline: 2.4073x; 1.7274x over previous
#include <cuda_runtime.h>
#include <cuda_fp16.h>
#include <cstdint>

// Zonotope propagation: D=1024 -> H=4096 -> H=4096 -> O=10
// E2 = W2 @ Baug via single-pass fp16 mma.sync (fp32 acc), rel_err ~6e-6.
// R16: revert k3 to clean R12 version (do_tv fusion caused reg spills);
//      restore side-stream k3b; k5 latency fix: KS3=64 (4 CTAs/SM) + unroll 4.

#define DD 1024
#define HH 4096
#define OO 10
#define NE 1024
#define NC3 1027
#define SE3 1056
#define KS3 64
#define KCH 64           // k-rows per k5 block
#define NJT 8

#define C_EPS   0.01f
#define C_MEAN  0.1307f
#define C_SIGMA 0.3081f

// ---- device scratch ----
__device__ float g_s1[HH];
__device__ float g_t1[HH];
__device__ float g_v1p[HH];
__device__ float g_d[DD];
__device__ __half g_BTh[(size_t)NE * HH];      // 8.4 MB
__device__ float g_E2s[(size_t)HH * NE];       // 16.8 MB
__device__ float g_rpart[NJT][HH];
__device__ float g_tcol[HH];
__device__ float g_vcol[HH];
__device__ float g_E3p[KS3 * OO * SE3];        // 2.7 MB

// ================= PTX helpers =================
static __device__ __forceinline__ uint32_t smem_u32(const void* p) {
    uint32_t a;
    asm("{ .reg .u64 t; cvta.to.shared.u64 t, %1; cvt.u32.u64 %0, t; }" : "=r"(a) : "l"(p));
    return a;
}
static __device__ __forceinline__ void cp16(uint32_t dst, const void* src) {
    asm volatile("cp.async.cg.shared.global [%0], [%1], 16;" :: "r"(dst), "l"(src));
}
static __device__ __forceinline__ void cp_commit() {
    asm volatile("cp.async.commit_group;" ::: "memory");
}
template <int N> static __device__ __forceinline__ void cp_wait() {
    asm volatile("cp.async.wait_group %0;" :: "n"(N) : "memory");
}
#define LDSM4(r0, r1, r2, r3, addr) \
    asm volatile("ldmatrix.sync.aligned.m8n8.x4.shared.b16 {%0,%1,%2,%3}, [%4];" \
                 : "=r"(r0), "=r"(r1), "=r"(r2), "=r"(r3) : "r"(addr))
#define MMA16816F(c, a, b) \
    asm volatile("mma.sync.aligned.m16n8k16.row.col.f32.f16.f16.f32 " \
                 "{%0,%1,%2,%3}, {%4,%5,%6,%7}, {%8,%9}, {%0,%1,%2,%3};" \
                 : "+f"((c)[0]), "+f"((c)[1]), "+f"((c)[2]), "+f"((c)[3]) \
                 : "r"((a)[0]), "r"((a)[1]), "r"((a)[2]), "r"((a)[3]), \
                   "r"((b)[0]), "r"((b)[1]))
#define STS128(addr, u0, u1, u2, u3) \
    asm volatile("st.shared.v4.b32 [%0], {%1,%2,%3,%4};" \
                 :: "r"(addr), "r"(u0), "r"(u1), "r"(u2), "r"(u3) : "memory")

static __device__ __forceinline__ void relu_params(float v, float r,
                                                   float& s, float& t, float& vn) {
    float u = v + r;
    float l = v - r;
    if (u <= 0.f)       { s = 0.f; t = 0.f; vn = 0.f; }
    else if (l < 0.f)   { float slope = u / (u - l); float term = (1.f - slope) * u * 0.5f;
                          s = slope; t = term; vn = slope * v + term; }
    else                { s = 1.f; t = 0.f; vn = v; }
}
static __device__ __forceinline__ uint32_t h2u(__half2 h) {
    return *reinterpret_cast<uint32_t*>(&h);
}

// ---- K01: fused init + layer-1 ----
__global__ void k01_layer1(const float* __restrict__ in,
                           const float* __restrict__ W1, const float* __restrict__ b1) {
    __shared__ __align__(16) float sv0[DD];
    __shared__ __align__(16) float sd[DD];
    const int tid = threadIdx.x;
    for (int j = tid; j < DD; j += 256) {
        float x  = in[j];
        float up = fminf(x + C_EPS, 1.f);
        float lo = fmaxf(x - C_EPS, 0.f);
        float val = up + lo;
        sv0[j] = (val - C_MEAN) / C_SIGMA;
        sd[j]  = up / C_SIGMA;
    }
    __syncthreads();
    if (blockIdx.x == 0) {
        for (int j = tid; j < DD; j += 256) g_d[j] = sd[j];
    }
    int row  = blockIdx.x * 8 + (tid >> 5);
    int lane = tid & 31;
    const float* w = W1 + (size_t)row * DD;
    float sv = 0.f, sr = 0.f;
    #pragma unroll
    for (int j = lane * 4; j < DD; j += 128) {
        float4 wv = *(const float4*)(w + j);
        float4 v  = *(const float4*)(sv0 + j);
        float4 dd = *(const float4*)(sd + j);
        sv += wv.x * v.x + wv.y * v.y + wv.z * v.z + wv.w * v.w;
        sr += fabsf(wv.x) * dd.x + fabsf(wv.y) * dd.y
            + fabsf(wv.z) * dd.z + fabsf(wv.w) * dd.w;
    }
    #pragma unroll
    for (int o = 16; o; o >>= 1) {
        sv += __shfl_xor_sync(0xffffffffu, sv, o);
        sr += __shfl_xor_sync(0xffffffffu, sr, o);
    }
    if (lane == 0) {
        float v = sv + b1[row];
        float s, t, vn;
        relu_params(v, sr, s, t, vn);
        g_s1[row] = s; g_t1[row] = t; g_v1p[row] = vn;
    }
}

// ---- K2b: BaugT in fp16, 64x64 tiles ----
__global__ void k2b_buildBT(const float* __restrict__ W1) {
    __shared__ float ts[64][65];
    const int k0 = blockIdx.x * 64;
    const int j0 = blockIdx.y * 64;
    const int tid = threadIdx.x;
    {
        const int kr = tid >> 4;
        const int c4 = (tid & 15) * 4;
        #pragma unroll
        for (int r = 0; r < 4; r++) {
            int krow = kr + r * 16;
            float s = g_s1[k0 + krow];
            float4 w = *(const float4*)(W1 + (size_t)(k0 + krow) * DD + j0 + c4);
            ts[krow][c4 + 0] = w.x * s;
            ts[krow][c4 + 1] = w.y * s;
            ts[krow][c4 + 2] = w.z * s;
            ts[krow][c4 + 3] = w.w * s;
        }
    }
    __syncthreads();
    #pragma unroll
    for (int w = 0; w < 2; w++) {
        int idx  = w * 256 + tid;
        int jrow = idx >> 3;
        int seg  = idx & 7;
        float dj = g_d[j0 + jrow];
        __half2 h[4];
        #pragma unroll
        for (int q = 0; q < 4; q++) {
            float a = ts[seg * 8 + q * 2][jrow] * dj;
            float b = ts[seg * 8 + q * 2 + 1][jrow] * dj;
            h[q] = __floats2half2_rn(a, b);
        }
        uint4 out = make_uint4(h2u(h[0]), h2u(h[1]), h2u(h[2]), h2u(h[3]));
        *(uint4*)(&g_BTh[(size_t)(j0 + jrow) * HH + k0 + seg * 8]) = out;
    }
}

// ---- K3b: t/v columns (side stream) ----
__global__ void k3b_tv(const float* __restrict__ W2) {
    int row  = blockIdx.x * 8 + (threadIdx.x >> 5);
    int lane = threadIdx.x & 31;
    const float* w = W2 + (size_t)row * HH;
    float st = 0.f, sv = 0.f;
    for (int j = lane * 4; j < HH; j += 128) {
        float4 wv = *(const float4*)(w + j);
        float4 tt = *(const float4*)(g_t1 + j);
        float4 vv = *(const float4*)(g_v1p + j);
        st += wv.x * tt.x + wv.y * tt.y + wv.z * tt.z + wv.w * tt.w;
        sv += wv.x * vv.x + wv.y * vv.y + wv.z * vv.z + wv.w * vv.w;
    }
    #pragma unroll
    for (int o = 16; o; o >>= 1) {
        st += __shfl_xor_sync(0xffffffffu, st, o);
        sv += __shfl_xor_sync(0xffffffffu, sv, o);
    }
    if (lane == 0) { g_tcol[row] = st; g_vcol[row] = sv; }
}

// ================== K3: fp16 GEMM (clean R12 version, regs 240) ==============
#define K3_STG 16384
#define K3_SMEM (3 * K3_STG)
#define NKG3 128

__global__ __launch_bounds__(128, 2) void k3_mma(const float* __restrict__ W2) {
    extern __shared__ __align__(1024) unsigned char sm[];
    __shared__ float rs[2][128];
    const int tid  = threadIdx.x;
    const int lane = tid & 31;
    const int wid  = tid >> 5;
    const int warp_m = wid & 1;
    const int warp_n = wid >> 1;
    const int j0 = blockIdx.x * 128;
    const int i0 = blockIdx.y * 128;
    const uint32_t sbase = smem_u32(sm);

    const int ra = (lane & 7) + (((lane >> 3) & 1) << 3);
    const int ha = lane >> 4;
    const int rb = (lane & 7) + ((lane >> 4) << 3);
    const int hb = (lane >> 3) & 1;
    uint32_t offA[4][2], offB[4][2];
    #pragma unroll
    for (int mf = 0; mf < 4; mf++)
        #pragma unroll
        for (int kk = 0; kk < 2; kk++) {
            int row = warp_m * 64 + mf * 16 + ra;
            int c   = kk * 2 + ha;
            offA[mf][kk] = row * 64 + ((c ^ ((row >> 1) & 3)) << 4);
        }
    #pragma unroll
    for (int nf4 = 0; nf4 < 4; nf4++)
        #pragma unroll
        for (int kk = 0; kk < 2; kk++) {
            int row = warp_n * 64 + nf4 * 16 + rb;
            int c   = kk * 2 + hb;
            offB[nf4][kk] = 8192 + row * 64 + ((c ^ ((row >> 1) & 3)) << 4);
        }

    int crow[4], ccol[4];
    uint32_t csw[4];
    #pragma unroll
    for (int s = 0; s < 4; s++) {
        int q = s * 128 + tid;
        crow[s] = q >> 2; ccol[s] = q & 3;
        csw[s] = crow[s] * 64 + ((ccol[s] ^ ((crow[s] >> 1) & 3)) << 4);
    }

    float4 aA[4][2];
    auto ldgA = [&](int kg) {
        const int kgo = kg * 32;
        #pragma unroll
        for (int s = 0; s < 4; s++) {
            const float* gp = W2 + (size_t)(i0 + crow[s]) * HH + kgo + ccol[s] * 8;
            aA[s][0] = *(const float4*)gp;
            aA[s][1] = *(const float4*)(gp + 4);
        }
    };
    auto stsA = [&](int stage) {
        const uint32_t base = sbase + stage * K3_STG;
        #pragma unroll
        for (int s = 0; s < 4; s++) {
            __half2 h0 = __floats2half2_rn(aA[s][0].x, aA[s][0].y);
            __half2 h1 = __floats2half2_rn(aA[s][0].z, aA[s][0].w);
            __half2 h2 = __floats2half2_rn(aA[s][1].x, aA[s][1].y);
            __half2 h3 = __floats2half2_rn(aA[s][1].z, aA[s][1].w);
            STS128(base + csw[s], h2u(h0), h2u(h1), h2u(h2), h2u(h3));
        }
    };
    auto cpB = [&](int stage, int kg) {
        const uint32_t base = sbase + stage * K3_STG + 8192;
        const int kgo = kg * 32;
        #pragma unroll
        for (int s = 0; s < 4; s++)
            cp16(base + csw[s], g_BTh + (size_t)(j0 + crow[s]) * HH + kgo + ccol[s] * 8);
        cp_commit();
    };

    float acc[4][8][4];
    #pragma unroll
    for (int mf = 0; mf < 4; mf++)
        #pragma unroll
        for (int nf = 0; nf < 8; nf++)
            #pragma unroll
            for (int q = 0; q < 4; q++) acc[mf][nf][q] = 0.f;

    ldgA(0); stsA(0); cpB(0, 0);
    ldgA(1); stsA(1); cpB(1, 1);
    ldgA(2);

    for (int kg = 0; kg < NKG3; ++kg) {
        if (kg + 1 == NKG3) cp_wait<0>();
        else                cp_wait<1>();
        __syncthreads();
        if (kg + 2 < NKG3) {
            const int ps = (kg + 2) % 3;
            stsA(ps);
            if (kg + 3 < NKG3) ldgA(kg + 3);
            cpB(ps, kg + 2);
        }
        const uint32_t base = sbase + (kg % 3) * K3_STG;
        #pragma unroll
        for (int kk = 0; kk < 2; kk++) {
            uint32_t a[4][4], bh[8][2];
            #pragma unroll
            for (int mf = 0; mf < 4; mf++)
                LDSM4(a[mf][0], a[mf][1], a[mf][2], a[mf][3], base + offA[mf][kk]);
            #pragma unroll
            for (int nf4 = 0; nf4 < 4; nf4++) {
                uint32_t r0, r1, r2, r3;
                LDSM4(r0, r1, r2, r3, base + offB[nf4][kk]);
                bh[nf4 * 2][0] = r0;     bh[nf4 * 2][1] = r1;
                bh[nf4 * 2 + 1][0] = r2; bh[nf4 * 2 + 1][1] = r3;
            }
            #pragma unroll
            for (int mf = 0; mf < 4; mf++)
                #pragma unroll
                for (int nf = 0; nf < 8; nf++)
                    MMA16816F(acc[mf][nf], a[mf], bh[nf]);
        }
    }

    // epilogue: store E2 tile + fused per-row |.| partial sums
    const int er = lane >> 2;
    const int ec = (lane & 3) * 2;
    #pragma unroll
    for (int mf = 0; mf < 4; mf++) {
        float sa = 0.f, sb = 0.f;
        #pragma unroll
        for (int nf = 0; nf < 8; nf++) {
            int row = i0 + warp_m * 64 + mf * 16 + er;
            int col = j0 + warp_n * 64 + nf * 8 + ec;
            *(float2*)(g_E2s + (size_t)row * NE + col)       = make_float2(acc[mf][nf][0], acc[mf][nf][1]);
            *(float2*)(g_E2s + (size_t)(row + 8) * NE + col) = make_float2(acc[mf][nf][2], acc[mf][nf][3]);
            sa += fabsf(acc[mf][nf][0]) + fabsf(acc[mf][nf][1]);
            sb += fabsf(acc[mf][nf][2]) + fabsf(acc[mf][nf][3]);
        }
        sa += __shfl_xor_sync(0xffffffffu, sa, 1);
        sa += __shfl_xor_sync(0xffffffffu, sa, 2);
        sb += __shfl_xor_sync(0xffffffffu, sb, 1);
        sb += __shfl_xor_sync(0xffffffffu, sb, 2);
        if ((lane & 3) == 0) {
            rs[warp_n][warp_m * 64 + mf * 16 + er]     = sa;
            rs[warp_n][warp_m * 64 + mf * 16 + 8 + er] = sb;
        }
    }
    __syncthreads();
    {
        int row = tid;
        float v = rs[0][row] + rs[1][row];
        g_rpart[blockIdx.x][i0 + row] = v;
    }
}

// ---- K5: layer-3 partial GEMM, KCH=64 chunks + inline ReLU params ----
__global__ void k5_e3(const float* __restrict__ W3, const float* __restrict__ b2) {
    __shared__ float w3s[OO][KCH];
    __shared__ float s2s[KCH];
    __shared__ float t2s[KCH];
    __shared__ float v2s[KCH];
    const int jt = blockIdx.x, ks = blockIdx.y;
    const int k0 = ks * KCH;
    const int tid = threadIdx.x;

    // inline relu params for this k-chunk (threads 0..63)
    if (tid < KCH) {
        int row = k0 + tid;
        float sr = 0.f;
        #pragma unroll
        for (int p = 0; p < NJT; p++) sr += g_rpart[p][row];
        sr += fabsf(g_tcol[row]);
        float v = g_vcol[row] + b2[row];
        float s, t, vn;
        relu_params(v, sr, s, t, vn);
        s2s[tid] = s; t2s[tid] = t; v2s[tid] = vn;
    }
    for (int idx = tid; idx < OO * KCH; idx += 128) {
        int i = idx / KCH, kk = idx % KCH;
        w3s[i][kk] = W3[(size_t)i * HH + k0 + kk];
    }
    __syncthreads();

    const int j = jt * 128 + tid;
    float acc[OO];
    #pragma unroll
    for (int i = 0; i < OO; i++) acc[i] = 0.f;

    if (j < 1024) {
        const float* e = g_E2s + (size_t)k0 * NE + j;
        #pragma unroll 4
        for (int kk = 0; kk < KCH; ++kk) {
            float bval = s2s[kk] * e[(size_t)kk * NE];
            #pragma unroll
            for (int i = 0; i < OO; i++) acc[i] += w3s[i][kk] * bval;
        }
    } else if (j == 1024) {
        for (int kk = 0; kk < KCH; ++kk) {
            float bval = s2s[kk] * g_tcol[k0 + kk];
            #pragma unroll
            for (int i = 0; i < OO; i++) acc[i] += w3s[i][kk] * bval;
        }
    } else if (j == 1025) {
        for (int kk = 0; kk < KCH; ++kk) {
            float bval = t2s[kk];
            #pragma unroll
            for (int i = 0; i < OO; i++) acc[i] += w3s[i][kk] * bval;
        }
    } else if (j == 1026) {
        for (int kk = 0; kk < KCH; ++kk) {
            float bval = v2s[kk];
            #pragma unroll
            for (int i = 0; i < OO; i++) acc[i] += w3s[i][kk] * bval;
        }
    }
    if (j < NC3) {
        #pragma unroll
        for (int i = 0; i < OO; i++)
            g_E3p[((size_t)ks * OO + i) * SE3 + j] = acc[i];
    }
}

// ---- K6: final bounds (10 parallel blocks) ----
__global__ void k6_final(const float* __restrict__ b3, float* __restrict__ out) {
    const int i = blockIdx.x;
    const int tid = threadIdx.x;
    __shared__ float red[256];
    __shared__ float vsh;
    float racc = 0.f;
    for (int j = tid; j < NC3; j += 256) {
        float s = 0.f;
        #pragma unroll
        for (int ks = 0; ks < KS3; ks++) s += g_E3p[((size_t)ks * OO + i) * SE3 + j];
        if (j < 1026) racc += fabsf(s);
        else          vsh = s + b3[i];
    }
    red[tid] = racc;
    __syncthreads();
    for (int o = 128; o; o >>= 1) {
        if (tid < o) red[tid] += red[tid + o];
        __syncthreads();
    }
    if (tid == 0) {
        float v = vsh, r = red[0];
        out[i]      = v + r;
        out[10 + i] = v - r;
    }
}

extern "C" void kernel_launch(void* const* d_in, const int* in_sizes, int n_in,
                              void* d_out, int out_size) {
    const float* inputs = (const float*)d_in[0];
    const float* W1     = (const float*)d_in[1];
    const float* b1     = (const float*)d_in[2];
    const float* W2     = (const float*)d_in[3];
    const float* b2     = (const float*)d_in[4];
    const float* W3     = (const float*)d_in[5];
    const float* b3     = (const float*)d_in[6];
    float* out = (float*)d_out;

    static cudaStream_t sB = nullptr;
    static cudaEvent_t evK = nullptr, evB = nullptr;
    if (!sB) {
        cudaStreamCreateWithFlags(&sB, cudaStreamNonBlocking);
        cudaEventCreateWithFlags(&evK, cudaEventDisableTiming);
        cudaEventCreateWithFlags(&evB, cudaEventDisableTiming);
        cudaFuncSetAttribute(k3_mma, cudaFuncAttributeMaxDynamicSharedMemorySize, K3_SMEM);
    }

    // main chain
    k01_layer1<<<HH / 8, 256>>>(inputs, W1, b1);

    // fork: t/v matvec on side stream (needs k01 only)
    cudaEventRecord(evK, 0);
    cudaStreamWaitEvent(sB, evK, 0);
    k3b_tv<<<HH / 8, 256, 0, sB>>>(W2);
    cudaEventRecord(evB, sB);

    dim3 g2b(HH / 64, DD / 64);
    k2b_buildBT<<<g2b, 256>>>(W1);

    dim3 g3(NE / 128, HH / 128);
    k3_mma<<<g3, 128, K3_SMEM>>>(W2);

    cudaStreamWaitEvent(0, evB, 0);       // k5 needs tcol/vcol
    dim3 g5(9, KS3);
    k5_e3<<<g5, 128>>>(W3, b2);
    k6_final<<<OO, 256>>>(b3, out);
}